// round 12
// baseline (speedup 1.0000x reference)
#include <cuda_runtime.h>

// ---------------------------------------------------------------------------
// Device-global state. Finalizing block resets it each launch.
// ---------------------------------------------------------------------------
__device__ double   g_accum[2];   // [0]=img CE sum, [1]=cls CE sum
__device__ unsigned g_done;

typedef unsigned long long u64;

__device__ __forceinline__ float lg2f(float x) {
    float y; asm("lg2.approx.f32 %0,%1;" : "=f"(y) : "f"(x)); return y;
}
__device__ __forceinline__ float ex2f(float x) {
    float y; asm("ex2.approx.f32 %0,%1;" : "=f"(y) : "f"(x)); return y;
}
__device__ __forceinline__ u64 pk(float lo, float hi) {
    u64 r; asm("mov.b64 %0,{%1,%2};" : "=l"(r) : "f"(lo), "f"(hi)); return r;
}
__device__ __forceinline__ void upk(u64 v, float& lo, float& hi) {
    asm("mov.b64 {%0,%1},%2;" : "=f"(lo), "=f"(hi) : "l"(v));
}
__device__ __forceinline__ u64 fma2(u64 a, u64 b, u64 c) {
    u64 d; asm("fma.rn.f32x2 %0,%1,%2,%3;" : "=l"(d) : "l"(a), "l"(b), "l"(c)); return d;
}
__device__ __forceinline__ u64 mul2(u64 a, u64 b) {
    u64 d; asm("mul.rn.f32x2 %0,%1,%2;" : "=l"(d) : "l"(a), "l"(b)); return d;
}
__device__ __forceinline__ u64 add2(u64 a, u64 b) {
    u64 d; asm("add.rn.f32x2 %0,%1,%2;" : "=l"(d) : "l"(a), "l"(b)); return d;
}

// ---------------------------------------------------------------------------
// JAX threefry-2x32, key=(0,k1); ks2 = k1 ^ 0x1BD11BDA. Exact (k0=0 folded).
// Used ONLY for the tiny cls MC (1000 ciphers).
// ---------------------------------------------------------------------------
__device__ __forceinline__ void tf2x32_k0(unsigned k1, unsigned ks2,
                                          unsigned x0, unsigned x1,
                                          unsigned& o0, unsigned& o1) {
    x1 += k1;
#define TF_RND(R) { x0 += x1; x1 = __funnelshift_l(x1, x1, (R)); x1 ^= x0; }
    TF_RND(13) TF_RND(15) TF_RND(26) TF_RND(6)
    x0 += k1;  x1 += ks2 + 1u;
    TF_RND(17) TF_RND(29) TF_RND(16) TF_RND(24)
    x0 += ks2; x1 += 2u;
    TF_RND(13) TF_RND(15) TF_RND(26) TF_RND(6)
    x1 += k1 + 3u;
    TF_RND(17) TF_RND(29) TF_RND(16) TF_RND(24)
    x0 += k1;  x1 += ks2 + 4u;
    TF_RND(13) TF_RND(15) TF_RND(26) TF_RND(6)
    x0 += ks2; x1 += 5u;
#undef TF_RND
    o0 = x0; o1 = x1;
}

__device__ __forceinline__ float erfinv_xla(float x) {
    float w = -__logf(fmaf(-x, x, 1.0f));
    float p;
    if (w < 5.0f) {
        w = w - 2.5f;
        p = 2.81022636e-08f;
        p = fmaf(p, w, 3.43273939e-07f);
        p = fmaf(p, w, -3.5233877e-06f);
        p = fmaf(p, w, -4.39150654e-06f);
        p = fmaf(p, w, 0.00021858087f);
        p = fmaf(p, w, -0.00125372503f);
        p = fmaf(p, w, -0.00417768164f);
        p = fmaf(p, w, 0.246640727f);
        p = fmaf(p, w, 1.50140941f);
    } else {
        w = sqrtf(w) - 3.0f;
        p = -0.000200214257f;
        p = fmaf(p, w, 0.000100950558f);
        p = fmaf(p, w, 0.00134934322f);
        p = fmaf(p, w, -0.00367342844f);
        p = fmaf(p, w, 0.00573950773f);
        p = fmaf(p, w, -0.0076224613f);
        p = fmaf(p, w, 0.00943887047f);
        p = fmaf(p, w, 1.00167406f);
        p = fmaf(p, w, 2.83297682f);
    }
    return p * x;
}

__device__ __forceinline__ float bits_to_normal(unsigned b) {
    float u01 = __uint_as_float((b >> 9) | 0x3f800000u) - 1.0f;
    float x = fmaf(u01, 1.9999999403953552f, -0.99999994039535522f);
    x = fmaxf(x, -0.99999994039535522f);
    return 1.4142135381698608f * erfinv_xla(x);
}

__device__ __forceinline__ float ce3(float l0, float l1, float l2, float s,
                                     float e0, float e1, float e2,
                                     float t0, float t1, float t2, float ts) {
    float n0 = fmaf(e0, s, l0);
    float n1 = fmaf(e1, s, l1);
    float n2 = fmaf(e2, s, l2);
    float m  = fmaxf(n0, fmaxf(n1, n2));
    float s0 = n0 - m, s1 = n1 - m, s2 = n2 - m;
    float Z  = __expf(s0) + __expf(s1) + __expf(s2);
    float lZ = __logf(Z);
    return ts * lZ - (t0 * s0 + t1 * s1 + t2 * s2);
}

// Bit-matched MC for cls: thread tid handles (row n, t-pair (t, t+250)).
__device__ float cls_mc_work(const float* __restrict__ tru,
                             const float4* __restrict__ pred,
                             int N, int tid, unsigned k1) {
    int total = N * 250;
    if (tid >= total) return 0.0f;
    const unsigned ks2 = k1 ^ 0x1BD11BDAu;
    int n = tid / 250;
    int t = tid - n * 250;

    float4 p = pred[n];
    float l0 = p.x, l1 = p.y, l2 = p.z;
    float scale = sqrtf(__expf(p.w));
    float t0 = tru[3 * n + 0];
    float t1 = tru[3 * n + 1];
    float t2 = tru[3 * n + 2];
    float ts = t0 + t1 + t2;

    const unsigned half = (unsigned)N * 750u;
    unsigned base = ((unsigned)t * (unsigned)N + (unsigned)n) * 3u;

    float eA[3], eB[3];
#pragma unroll
    for (int c = 0; c < 3; c++) {
        unsigned b0, b1;
        tf2x32_k0(k1, ks2, base + (unsigned)c, half + base + (unsigned)c, b0, b1);
        eA[c] = bits_to_normal(b0);
        eB[c] = bits_to_normal(b1);
    }
    return ce3(l0, l1, l2, scale, eA[0], eA[1], eA[2], t0, t1, t2, ts)
         + ce3(l0, l1, l2, scale, eB[0], eB[1], eB[2], t0, t1, t2, ts);
}

// ---------------------------------------------------------------------------
// img path: E[CE] per pixel via 2-D midpoint Gaussian quadrature.
//   E[CE] = ts*(l0 + ln2 * E[G]) - (t0*l0 + t1*l1 + t2*l2)
//   G = lg2(1 + 2^t1 + 2^t2), t = L2E*(mu + s*L*u), L=[[s2,0],[1/s2,sqrt(3/2)]]
// 8 threads/pixel, 4 pixels/warp; n WARP-UNIFORM from warp-max s (redux).
// Grid: u_k = (k+0.5-n/2)*h; n = even(clamp(ceil(6*s_wmax), 6, 64));
// h = 9.2/n -> coverage +-4.6 sigma, h*s <= 1.533 (measured ~3.3e-4 total).
// Inner loop: packed f32x2 column pairs, geometric recurrences, 2 lg2/pair.
// Fast path n<=32 (s_wmax<=5.33): |t| < ~84 -> no clamps needed.
// Fallback n>32 (rare, warp-uniform): direct clamped scalar eval.
// Normalizer: sw1^2.
// ---------------------------------------------------------------------------
__device__ float img_quad_work(const float* __restrict__ tru,
                               const float4* __restrict__ pred,
                               int Nimg, int gtid) {
    int pix = gtid >> 3;
    int sub = gtid & 7;
    int valid = (pix < Nimg);
    if (!valid) pix = 0;            // keep lanes alive for the shuffles

    float4 p = pred[pix];
    float l0 = p.x, l1 = p.y, l2 = p.z, z = p.w;
    const float L2E  = 1.44269504089f;
    const float HL2E = 0.72134752044f;
    float s = ex2f(HL2E * z);       // e^{z/2}
    float sn = valid ? s : 0.0f;

    // Warp-uniform n from warp-max s (s>0 -> float bits are u32-monotonic).
    sn = __uint_as_float(__reduce_max_sync(0xffffffffu, __float_as_uint(sn)));

    int n = (int)ceilf(6.0f * sn);
    n = max(6, min(64, n));
    n += (n & 1);                   // even, for column pairing
    float h   = __fdividef(9.2f, (float)n);
    float u2s = (0.5f - 0.5f * (float)n) * h;   // first node (both dims)

    float m1 = (l1 - l0) * L2E;
    float m2 = (l2 - l0) * L2E;
    float a1 = 2.04044650f * s;     // sqrt(2)*L2E*s
    float a2 = 1.02022325f * s;     // L2E/sqrt(2)*s
    float a3 = 1.76697320f * s;     // sqrt(1.5)*L2E*s
    float a3h = a3 * h;
    float m2p = fmaf(a3, u2s, m2);  // t2 at column 0 (u1 term added per row)

    float hL  = L2E * h;
    float rho = ex2f(-hL * h);                      // e^{-h^2}
    float w20 = ex2f(-HL2E * u2s * u2s);            // column weight j=0
    float r20 = ex2f(-hL * fmaf(0.5f, h, u2s));     // w_{j+1}/w_j at j=0
    float w21 = w20 * r20;                          // column weight j=1

    float sw1 = 0.0f;
    float accg = 0.0f;

    if (n <= 32) {                                  // warp-uniform branch
        // Packed-pair recurrence constants (derived from one rho)
        float rho2 = rho * rho;                     // e^{-2h^2}
        float p0   = r20 * r20 * rho;               // w_{j+2}/w_j at j=0
        float p1   = p0 * rho2;                     // ... at j=1
        u64 P0 = pk(p0, p1);
        float rho4 = rho2 * rho2;
        u64 R4 = pk(rho4, rho4);                    // pair-ratio step
        float c2 = ex2f(a3h);                       // 2^t2 column ratio
        float c2sq = c2 * c2;
        u64 C2 = pk(c2sq, c2sq);

        u64 ACC = 0ull;
        int half = n >> 1;
        for (int i = sub; i < n; i += 8) {
            float u1 = fmaf((float)i, h, u2s);
            float w1 = ex2f(-HL2E * u1 * u1);
            float A  = 1.0f + ex2f(fmaf(a1, u1, m1));
            float E2a = ex2f(fmaf(a2, u1, m2p));
            float E2b = E2a * c2;
            u64 E2 = pk(E2a, E2b);
            u64 A2 = pk(A, A);
            u64 W  = pk(w1 * w20, w1 * w21);        // w1 folded in
            u64 P  = P0;
#pragma unroll 4
            for (int jj = 0; jj < half; jj++) {
                u64 S2 = add2(A2, E2);
                float Sa, Sb; upk(S2, Sa, Sb);
                u64 G2 = pk(lg2f(Sa), lg2f(Sb));
                ACC = fma2(W, G2, ACC);
                E2 = mul2(E2, C2);
                W  = mul2(W, P);
                P  = mul2(P, R4);
            }
            sw1 += w1;
        }
        float alo, ahi; upk(ACC, alo, ahi);
        accg = alo + ahi;
    } else {
        // Rare large-sigma fallback (warp-uniform): direct, clamped, scalar.
        for (int i = sub; i < n; i += 8) {
            float u1 = fmaf((float)i, h, u2s);
            float w1 = ex2f(-HL2E * u1 * u1);
            float t1 = fminf(fmaf(a1, u1, m1), 125.0f);
            float A  = 1.0f + ex2f(t1);
            float cj = fmaf(a2, u1, m2p);
            float w2 = w20, r2 = r20, acc = 0.0f;
            for (int j = 0; j < n; j++) {
                float G = lg2f(A + ex2f(fminf(cj, 125.0f)));
                acc = fmaf(w2, G, acc);
                cj += a3h;
                w2 *= r2;
                r2 *= rho;
            }
            accg = fmaf(w1, acc, accg);
            sw1 += w1;
        }
    }

    // Combine the 8 sub-threads of this pixel (aligned 8-lane groups).
#pragma unroll
    for (int o = 4; o > 0; o >>= 1) {
        accg += __shfl_down_sync(0xffffffffu, accg, o);
        sw1  += __shfl_down_sync(0xffffffffu, sw1, o);
    }

    float ce = 0.0f;
    if (sub == 0 && valid) {
        float t0  = tru[3 * pix + 0];
        float tc1 = tru[3 * pix + 1];
        float tc2 = tru[3 * pix + 2];
        float ts = t0 + tc1 + tc2;
        float meanLSE = fmaf(0.6931471805599453f, accg / (sw1 * sw1), l0);
        ce = ts * meanLSE - (t0 * l0 + tc1 * l1 + tc2 * l2);
    }
    return ce;
}

// ---------------------------------------------------------------------------
// Single fused kernel, 64-thread blocks (2 warps, 8 pixels) for fine-grained
// load balancing: block runtimes vary ~10x with warp-max n, and small blocks
// let the SM back-fill around stragglers. launch_bounds(64,24): 48 warps/SM.
// ---------------------------------------------------------------------------
__global__ __launch_bounds__(64, 24)
void fused_loss_kernel(const float* __restrict__ true_img,
                       const float4* __restrict__ pred_img,
                       const float* __restrict__ true_cls,
                       const float4* __restrict__ pred_cls,
                       const float* __restrict__ log_vars,
                       const float* __restrict__ w_img,
                       const float* __restrict__ w_cls,
                       float* __restrict__ out,
                       int Nimg, int Ncls, int Bimg) {
    int bid = blockIdx.x;
    float local;
    int accIdx;
    if (bid < Bimg) {
        local = img_quad_work(true_img, pred_img, Nimg, bid * 64 + threadIdx.x);
        accIdx = 0;
    } else {
        local = cls_mc_work(true_cls, pred_cls, Ncls,
                            (bid - Bimg) * 64 + threadIdx.x, 456u);
        accIdx = 1;
    }

    // Block reduction (2 warps)
#pragma unroll
    for (int o = 16; o > 0; o >>= 1)
        local += __shfl_down_sync(0xffffffffu, local, o);

    __shared__ float warpsum[2];
    int lane = threadIdx.x & 31;
    int w    = threadIdx.x >> 5;
    if (lane == 0) warpsum[w] = local;
    __syncthreads();
    if (threadIdx.x == 0) {
        float v = warpsum[0] + warpsum[1];
        atomicAdd(&g_accum[accIdx], (double)v);

        __threadfence();
        unsigned ticket = atomicAdd(&g_done, 1u);
        if (ticket == (unsigned)(gridDim.x - 1)) {
            __threadfence();
            double li_d = g_accum[0] / (double)Nimg;           // quadrature
            double lc_d = g_accum[1] / (500.0 * (double)Ncls); // MC
            float mwi = (w_img[0] + w_img[1] + w_img[2]) * (1.0f / 3.0f);
            float mwc = (w_cls[0] + w_cls[1] + w_cls[2]) * (1.0f / 3.0f);
            float li = (float)li_d * mwi;
            float lc = (float)lc_d * mwc;
            float lv0 = log_vars[0], lv1 = log_vars[1];
            out[0] = expf(-lv0) * li + lv0 + expf(-lv1) * lc + lv1;
            g_accum[0] = 0.0;
            g_accum[1] = 0.0;
            g_done = 0u;
        }
    }
}

// ---------------------------------------------------------------------------
// kernel_launch — ONE kernel, graph-capturable, allocation-free.
// ---------------------------------------------------------------------------
extern "C" void kernel_launch(void* const* d_in, const int* in_sizes, int n_in,
                              void* d_out, int out_size) {
    (void)n_in; (void)out_size;
    const float* true_img = (const float*)d_in[0];
    const float* pred_img = (const float*)d_in[1];
    const float* true_cls = (const float*)d_in[2];
    const float* pred_cls = (const float*)d_in[3];
    const float* log_vars = (const float*)d_in[4];
    const float* w_img    = (const float*)d_in[5];
    const float* w_cls    = (const float*)d_in[6];

    int Nimg = in_sizes[1] / 4;   // 65536 pixels
    int Ncls = in_sizes[3] / 4;   // 4 rows

    int Bimg = (Nimg * 8 + 63) / 64;      // 8 threads/pixel, 8 pixels/block
    int Bcls = (Ncls * 250 + 63) / 64;    // exact-MC path

    fused_loss_kernel<<<Bimg + Bcls, 64>>>(
        true_img, (const float4*)pred_img,
        true_cls, (const float4*)pred_cls,
        log_vars, w_img, w_cls, (float*)d_out,
        Nimg, Ncls, Bimg);
}

// round 13
// speedup vs baseline: 1.2429x; 1.2429x over previous
#include <cuda_runtime.h>

// ---------------------------------------------------------------------------
// Device-global state. Finalizing block resets it each launch.
// ---------------------------------------------------------------------------
__device__ double   g_accum[2];   // [0]=img CE sum, [1]=cls CE sum
__device__ unsigned g_done;

typedef unsigned long long u64;

__device__ __forceinline__ float lg2f(float x) {
    float y; asm("lg2.approx.f32 %0,%1;" : "=f"(y) : "f"(x)); return y;
}
__device__ __forceinline__ float ex2f(float x) {
    float y; asm("ex2.approx.f32 %0,%1;" : "=f"(y) : "f"(x)); return y;
}
__device__ __forceinline__ u64 pk(float lo, float hi) {
    u64 r; asm("mov.b64 %0,{%1,%2};" : "=l"(r) : "f"(lo), "f"(hi)); return r;
}
__device__ __forceinline__ void upk(u64 v, float& lo, float& hi) {
    asm("mov.b64 {%0,%1},%2;" : "=f"(lo), "=f"(hi) : "l"(v));
}
__device__ __forceinline__ u64 fma2(u64 a, u64 b, u64 c) {
    u64 d; asm("fma.rn.f32x2 %0,%1,%2,%3;" : "=l"(d) : "l"(a), "l"(b), "l"(c)); return d;
}
__device__ __forceinline__ u64 mul2(u64 a, u64 b) {
    u64 d; asm("mul.rn.f32x2 %0,%1,%2;" : "=l"(d) : "l"(a), "l"(b)); return d;
}
__device__ __forceinline__ u64 add2(u64 a, u64 b) {
    u64 d; asm("add.rn.f32x2 %0,%1,%2;" : "=l"(d) : "l"(a), "l"(b)); return d;
}

// ---------------------------------------------------------------------------
// JAX threefry-2x32, key=(0,k1); ks2 = k1 ^ 0x1BD11BDA. Exact (k0=0 folded).
// Used ONLY for the tiny cls MC (1000 ciphers).
// ---------------------------------------------------------------------------
__device__ __forceinline__ void tf2x32_k0(unsigned k1, unsigned ks2,
                                          unsigned x0, unsigned x1,
                                          unsigned& o0, unsigned& o1) {
    x1 += k1;
#define TF_RND(R) { x0 += x1; x1 = __funnelshift_l(x1, x1, (R)); x1 ^= x0; }
    TF_RND(13) TF_RND(15) TF_RND(26) TF_RND(6)
    x0 += k1;  x1 += ks2 + 1u;
    TF_RND(17) TF_RND(29) TF_RND(16) TF_RND(24)
    x0 += ks2; x1 += 2u;
    TF_RND(13) TF_RND(15) TF_RND(26) TF_RND(6)
    x1 += k1 + 3u;
    TF_RND(17) TF_RND(29) TF_RND(16) TF_RND(24)
    x0 += k1;  x1 += ks2 + 4u;
    TF_RND(13) TF_RND(15) TF_RND(26) TF_RND(6)
    x0 += ks2; x1 += 5u;
#undef TF_RND
    o0 = x0; o1 = x1;
}

__device__ __forceinline__ float erfinv_xla(float x) {
    float w = -__logf(fmaf(-x, x, 1.0f));
    float p;
    if (w < 5.0f) {
        w = w - 2.5f;
        p = 2.81022636e-08f;
        p = fmaf(p, w, 3.43273939e-07f);
        p = fmaf(p, w, -3.5233877e-06f);
        p = fmaf(p, w, -4.39150654e-06f);
        p = fmaf(p, w, 0.00021858087f);
        p = fmaf(p, w, -0.00125372503f);
        p = fmaf(p, w, -0.00417768164f);
        p = fmaf(p, w, 0.246640727f);
        p = fmaf(p, w, 1.50140941f);
    } else {
        w = sqrtf(w) - 3.0f;
        p = -0.000200214257f;
        p = fmaf(p, w, 0.000100950558f);
        p = fmaf(p, w, 0.00134934322f);
        p = fmaf(p, w, -0.00367342844f);
        p = fmaf(p, w, 0.00573950773f);
        p = fmaf(p, w, -0.0076224613f);
        p = fmaf(p, w, 0.00943887047f);
        p = fmaf(p, w, 1.00167406f);
        p = fmaf(p, w, 2.83297682f);
    }
    return p * x;
}

__device__ __forceinline__ float bits_to_normal(unsigned b) {
    float u01 = __uint_as_float((b >> 9) | 0x3f800000u) - 1.0f;
    float x = fmaf(u01, 1.9999999403953552f, -0.99999994039535522f);
    x = fmaxf(x, -0.99999994039535522f);
    return 1.4142135381698608f * erfinv_xla(x);
}

__device__ __forceinline__ float ce3(float l0, float l1, float l2, float s,
                                     float e0, float e1, float e2,
                                     float t0, float t1, float t2, float ts) {
    float n0 = fmaf(e0, s, l0);
    float n1 = fmaf(e1, s, l1);
    float n2 = fmaf(e2, s, l2);
    float m  = fmaxf(n0, fmaxf(n1, n2));
    float s0 = n0 - m, s1 = n1 - m, s2 = n2 - m;
    float Z  = __expf(s0) + __expf(s1) + __expf(s2);
    float lZ = __logf(Z);
    return ts * lZ - (t0 * s0 + t1 * s1 + t2 * s2);
}

// Bit-matched MC for cls: thread tid handles (row n, t-pair (t, t+250)).
__device__ float cls_mc_work(const float* __restrict__ tru,
                             const float4* __restrict__ pred,
                             int N, int tid, unsigned k1) {
    int total = N * 250;
    if (tid >= total) return 0.0f;
    const unsigned ks2 = k1 ^ 0x1BD11BDAu;
    int n = tid / 250;
    int t = tid - n * 250;

    float4 p = pred[n];
    float l0 = p.x, l1 = p.y, l2 = p.z;
    float scale = sqrtf(__expf(p.w));
    float t0 = tru[3 * n + 0];
    float t1 = tru[3 * n + 1];
    float t2 = tru[3 * n + 2];
    float ts = t0 + t1 + t2;

    const unsigned half = (unsigned)N * 750u;
    unsigned base = ((unsigned)t * (unsigned)N + (unsigned)n) * 3u;

    float eA[3], eB[3];
#pragma unroll
    for (int c = 0; c < 3; c++) {
        unsigned b0, b1;
        tf2x32_k0(k1, ks2, base + (unsigned)c, half + base + (unsigned)c, b0, b1);
        eA[c] = bits_to_normal(b0);
        eB[c] = bits_to_normal(b1);
    }
    return ce3(l0, l1, l2, scale, eA[0], eA[1], eA[2], t0, t1, t2, ts)
         + ce3(l0, l1, l2, scale, eB[0], eB[1], eB[2], t0, t1, t2, ts);
}

// ---------------------------------------------------------------------------
// img path: E[CE] per pixel via 2-D midpoint Gaussian quadrature.
// Identical math to the 18.5us version: 8 lanes/pixel, 4 pixels/warp,
// n WARP-UNIFORM from warp-max s; packed f32x2 column-pair inner loop;
// n = even(clamp(ceil(6*s_wmax), 6, 64)); h = 9.2/n; normalizer sw1^2.
// ---------------------------------------------------------------------------
__device__ float img_quad_work(const float* __restrict__ tru,
                               const float4* __restrict__ pred,
                               int Nimg, int pix, int sub) {
    int valid = (pix < Nimg);
    if (!valid) pix = 0;            // keep lanes alive for the shuffles

    float4 p = pred[pix];
    float l0 = p.x, l1 = p.y, l2 = p.z, z = p.w;
    const float L2E  = 1.44269504089f;
    const float HL2E = 0.72134752044f;
    float s = ex2f(HL2E * z);       // e^{z/2}
    float sn = valid ? s : 0.0f;

    // Warp-uniform n from warp-max s (s>0 -> float bits are u32-monotonic).
    sn = __uint_as_float(__reduce_max_sync(0xffffffffu, __float_as_uint(sn)));

    int n = (int)ceilf(6.0f * sn);
    n = max(6, min(64, n));
    n += (n & 1);                   // even, for column pairing
    float h   = __fdividef(9.2f, (float)n);
    float u2s = (0.5f - 0.5f * (float)n) * h;   // first node (both dims)

    float m1 = (l1 - l0) * L2E;
    float m2 = (l2 - l0) * L2E;
    float a1 = 2.04044650f * s;     // sqrt(2)*L2E*s
    float a2 = 1.02022325f * s;     // L2E/sqrt(2)*s
    float a3 = 1.76697320f * s;     // sqrt(1.5)*L2E*s
    float a3h = a3 * h;
    float m2p = fmaf(a3, u2s, m2);  // t2 at column 0 (u1 term added per row)

    float hL  = L2E * h;
    float rho = ex2f(-hL * h);                      // e^{-h^2}
    float w20 = ex2f(-HL2E * u2s * u2s);            // column weight j=0
    float r20 = ex2f(-hL * fmaf(0.5f, h, u2s));     // w_{j+1}/w_j at j=0
    float w21 = w20 * r20;                          // column weight j=1

    float sw1 = 0.0f;
    float accg = 0.0f;

    if (n <= 32) {                                  // warp-uniform branch
        float rho2 = rho * rho;                     // e^{-2h^2}
        float p0   = r20 * r20 * rho;               // w_{j+2}/w_j at j=0
        float p1   = p0 * rho2;                     // ... at j=1
        u64 P0 = pk(p0, p1);
        float rho4 = rho2 * rho2;
        u64 R4 = pk(rho4, rho4);                    // pair-ratio step
        float c2 = ex2f(a3h);                       // 2^t2 column ratio
        float c2sq = c2 * c2;
        u64 C2 = pk(c2sq, c2sq);

        u64 ACC = 0ull;
        int half = n >> 1;
        for (int i = sub; i < n; i += 8) {
            float u1 = fmaf((float)i, h, u2s);
            float w1 = ex2f(-HL2E * u1 * u1);
            float A  = 1.0f + ex2f(fmaf(a1, u1, m1));
            float E2a = ex2f(fmaf(a2, u1, m2p));
            float E2b = E2a * c2;
            u64 E2 = pk(E2a, E2b);
            u64 A2 = pk(A, A);
            u64 W  = pk(w1 * w20, w1 * w21);        // w1 folded in
            u64 P  = P0;
#pragma unroll 4
            for (int jj = 0; jj < half; jj++) {
                u64 S2 = add2(A2, E2);
                float Sa, Sb; upk(S2, Sa, Sb);
                u64 G2 = pk(lg2f(Sa), lg2f(Sb));
                ACC = fma2(W, G2, ACC);
                E2 = mul2(E2, C2);
                W  = mul2(W, P);
                P  = mul2(P, R4);
            }
            sw1 += w1;
        }
        float alo, ahi; upk(ACC, alo, ahi);
        accg = alo + ahi;
    } else {
        // Rare large-sigma fallback (warp-uniform): direct, clamped, scalar.
        for (int i = sub; i < n; i += 8) {
            float u1 = fmaf((float)i, h, u2s);
            float w1 = ex2f(-HL2E * u1 * u1);
            float t1 = fminf(fmaf(a1, u1, m1), 125.0f);
            float A  = 1.0f + ex2f(t1);
            float cj = fmaf(a2, u1, m2p);
            float w2 = w20, r2 = r20, acc = 0.0f;
            for (int j = 0; j < n; j++) {
                float G = lg2f(A + ex2f(fminf(cj, 125.0f)));
                acc = fmaf(w2, G, acc);
                cj += a3h;
                w2 *= r2;
                r2 *= rho;
            }
            accg = fmaf(w1, acc, accg);
            sw1 += w1;
        }
    }

    // Combine the 8 sub-threads of this pixel (aligned 8-lane groups).
#pragma unroll
    for (int o = 4; o > 0; o >>= 1) {
        accg += __shfl_down_sync(0xffffffffu, accg, o);
        sw1  += __shfl_down_sync(0xffffffffu, sw1, o);
    }

    float ce = 0.0f;
    if (sub == 0 && valid) {
        float t0  = tru[3 * pix + 0];
        float tc1 = tru[3 * pix + 1];
        float tc2 = tru[3 * pix + 2];
        float ts = t0 + tc1 + tc2;
        float meanLSE = fmaf(0.6931471805599453f, accg / (sw1 * sw1), l0);
        ce = ts * meanLSE - (t0 * l0 + tc1 * l1 + tc2 * l2);
    }
    return ce;
}

// ---------------------------------------------------------------------------
// Persistent single-wave kernel: 912 blocks (152 SMs x 6) x 256 threads,
// warps loop over warp-tasks with stride totalWarps. Tasks 0..clsT-1 are
// cls MC warp-chunks (32 threads each); the rest are img tasks (4 pixels).
// One wave -> no wave-quantization tail; each warp sums 2-3 tasks ->
// straggler smoothing. Math identical to the 18.5us kernel.
// ---------------------------------------------------------------------------
__global__ __launch_bounds__(256, 6)
void fused_loss_kernel(const float* __restrict__ true_img,
                       const float4* __restrict__ pred_img,
                       const float* __restrict__ true_cls,
                       const float4* __restrict__ pred_cls,
                       const float* __restrict__ log_vars,
                       const float* __restrict__ w_img,
                       const float* __restrict__ w_cls,
                       float* __restrict__ out,
                       int Nimg, int Ncls, int clsT, int totalT) {
    int lane  = threadIdx.x & 31;
    int wrp   = threadIdx.x >> 5;
    int gwarp = blockIdx.x * 8 + wrp;
    int nwarp = gridDim.x * 8;

    float limg = 0.0f, lcls = 0.0f;
    for (int task = gwarp; task < totalT; task += nwarp) {
        if (task < clsT) {
            lcls += cls_mc_work(true_cls, pred_cls, Ncls,
                                task * 32 + lane, 456u);
        } else {
            int it  = task - clsT;
            int pix = it * 4 + (lane >> 3);
            limg += img_quad_work(true_img, pred_img, Nimg, pix, lane & 7);
        }
    }

    // Block reduction of both partial sums.
#pragma unroll
    for (int o = 16; o > 0; o >>= 1) {
        limg += __shfl_down_sync(0xffffffffu, limg, o);
        lcls += __shfl_down_sync(0xffffffffu, lcls, o);
    }
    __shared__ float wsum[8][2];
    if (lane == 0) { wsum[wrp][0] = limg; wsum[wrp][1] = lcls; }
    __syncthreads();
    if (threadIdx.x == 0) {
        float vi = 0.0f, vc = 0.0f;
#pragma unroll
        for (int i = 0; i < 8; i++) { vi += wsum[i][0]; vc += wsum[i][1]; }
        atomicAdd(&g_accum[0], (double)vi);
        atomicAdd(&g_accum[1], (double)vc);

        __threadfence();
        unsigned ticket = atomicAdd(&g_done, 1u);
        if (ticket == (unsigned)(gridDim.x - 1)) {
            __threadfence();
            double li_d = g_accum[0] / (double)Nimg;           // quadrature
            double lc_d = g_accum[1] / (500.0 * (double)Ncls); // MC
            float mwi = (w_img[0] + w_img[1] + w_img[2]) * (1.0f / 3.0f);
            float mwc = (w_cls[0] + w_cls[1] + w_cls[2]) * (1.0f / 3.0f);
            float li = (float)li_d * mwi;
            float lc = (float)lc_d * mwc;
            float lv0 = log_vars[0], lv1 = log_vars[1];
            out[0] = expf(-lv0) * li + lv0 + expf(-lv1) * lc + lv1;
            g_accum[0] = 0.0;
            g_accum[1] = 0.0;
            g_done = 0u;
        }
    }
}

// ---------------------------------------------------------------------------
// kernel_launch — ONE kernel, graph-capturable, allocation-free.
// ---------------------------------------------------------------------------
extern "C" void kernel_launch(void* const* d_in, const int* in_sizes, int n_in,
                              void* d_out, int out_size) {
    (void)n_in; (void)out_size;
    const float* true_img = (const float*)d_in[0];
    const float* pred_img = (const float*)d_in[1];
    const float* true_cls = (const float*)d_in[2];
    const float* pred_cls = (const float*)d_in[3];
    const float* log_vars = (const float*)d_in[4];
    const float* w_img    = (const float*)d_in[5];
    const float* w_cls    = (const float*)d_in[6];

    int Nimg = in_sizes[1] / 4;   // 65536 pixels
    int Ncls = in_sizes[3] / 4;   // 4 rows

    int clsT  = (Ncls * 250 + 31) / 32;        // 32 cls warp-tasks
    int imgT  = (Nimg + 3) / 4;                // 16384 img warp-tasks
    int totalT = clsT + imgT;

    int blocks = 152 * 6;                      // one wave on GB300 (152 SMs)

    fused_loss_kernel<<<blocks, 256>>>(
        true_img, (const float4*)pred_img,
        true_cls, (const float4*)pred_cls,
        log_vars, w_img, w_cls, (float*)d_out,
        Nimg, Ncls, clsT, totalT);
}